// round 1
// baseline (speedup 1.0000x reference)
#include <cuda_runtime.h>
#include <math.h>

#define NB 64
#define CC 256
#define TT 64
#define VV 25
#define HID 16
#define NCV (NB*CC)            // 16384 (n,c) chunks
#define CHUNK (TT*VV)          // 1600 floats per (n,c)
#define TOTAL (NB*CC*TT*VV)    // 26214400

// scratch (allocation-free rule: __device__ globals)
__device__ float g_avg[NCV];
__device__ float g_mx[NCV];
__device__ float g_gates[NB * 5 * CC];

// output joint -> input joint (TORSO, LEFT_HAND, LEFT_LEG, RIGHT_HAND, RIGHT_LEG)
__constant__ int c_perm[VV] = {0,1,2,3,20,  8,9,10,11,23,24,  16,17,18,19,  4,5,6,7,21,22,  12,13,14,15};
__constant__ int c_grp[VV]  = {0,0,0,0,0,   1,1,1,1,1,1,      2,2,2,2,      3,3,3,3,3,3,    4,4,4,4};

// ---------------- K1: torso mean/max over (T, {0,1,2,3,20}) per (n,c) ----------------
// one warp per (n,c); lane handles t=lane and t=lane+32
__global__ void reduce_kernel(const float* __restrict__ x) {
    int gwarp = (blockIdx.x * blockDim.x + threadIdx.x) >> 5;
    int lane  = threadIdx.x & 31;
    if (gwarp >= NCV) return;
    const float* base = x + (size_t)gwarp * CHUNK;
    float s = 0.f, m = -INFINITY;
#pragma unroll
    for (int half = 0; half < 2; half++) {
        const float* row = base + (lane + half * 32) * VV;
        float v0 = row[0], v1 = row[1], v2 = row[2], v3 = row[3], v4 = row[20];
        s += (v0 + v1) + (v2 + v3) + v4;
        m = fmaxf(m, fmaxf(fmaxf(v0, v1), fmaxf(fmaxf(v2, v3), v4)));
    }
#pragma unroll
    for (int o = 16; o; o >>= 1) {
        s += __shfl_xor_sync(0xffffffffu, s, o);
        m = fmaxf(m, __shfl_xor_sync(0xffffffffu, m, o));
    }
    if (lane == 0) {
        g_avg[gwarp] = s * (1.0f / 320.0f);
        g_mx[gwarp]  = m;
    }
}

// ---------------- K2: per-(n,group) MLP -> gates ----------------
// gate[n,f,c] = sigmoid( (relu(W1·avg+b1) + relu(W1·mx+b1)) · W2[c,:] + 2*b2[c] )
__global__ void mlp_kernel(const float* __restrict__ W1, const float* __restrict__ b1,
                           const float* __restrict__ W2, const float* __restrict__ b2) {
    int blk = blockIdx.x;          // n*5 + f
    int n = blk / 5, f = blk % 5;
    __shared__ float pa[CC], pm[CC], hs[HID];
    int tid = threadIdx.x;
    pa[tid] = g_avg[n * CC + tid];
    pm[tid] = g_mx[n * CC + tid];
    __syncthreads();

    int w = tid >> 5, lane = tid & 31;   // 8 warps, 2 hidden units each
#pragma unroll
    for (int hh = 0; hh < 2; hh++) {
        int h = w * 2 + hh;
        const float* w1row = W1 + (f * HID + h) * CC;
        float sa = 0.f, sm = 0.f;
#pragma unroll
        for (int c = lane; c < CC; c += 32) {
            float wv = w1row[c];
            sa = fmaf(wv, pa[c], sa);
            sm = fmaf(wv, pm[c], sm);
        }
#pragma unroll
        for (int o = 16; o; o >>= 1) {
            sa += __shfl_xor_sync(0xffffffffu, sa, o);
            sm += __shfl_xor_sync(0xffffffffu, sm, o);
        }
        if (lane == 0) {
            float b = b1[f * HID + h];
            hs[h] = fmaxf(sa + b, 0.f) + fmaxf(sm + b, 0.f);
        }
    }
    __syncthreads();

    const float* w2row = W2 + ((size_t)f * CC + tid) * HID;
    float o = 2.0f * b2[f * CC + tid];
#pragma unroll
    for (int h = 0; h < HID; h++) o = fmaf(hs[h], w2row[h], o);
    g_gates[n * (5 * CC) + f * CC + tid] = 1.0f / (1.0f + expf(-o));
}

// ---------------- K3: out[n,c,t,j] = x[n,c,t,perm[j]] * gate[n,grp[j],c] ----------------
// flat, float4-vectorized stores; 4B permuted reads (full sector utilization)
__global__ void scale_kernel(const float* __restrict__ x, float* __restrict__ out) {
    unsigned gid = blockIdx.x * blockDim.x + threadIdx.x;
    unsigned e0 = gid * 4u;
    if (e0 >= (unsigned)TOTAL) return;
    float r[4];
#pragma unroll
    for (int k = 0; k < 4; k++) {
        unsigned ek  = e0 + k;
        unsigned nc  = ek / CHUNK;            // (n*256 + c)
        unsigned rem = ek - nc * CHUNK;
        unsigned t   = rem / VV;
        unsigned j   = rem - t * VV;
        float v = __ldg(x + (size_t)nc * CHUNK + t * VV + c_perm[j]);
        float g = g_gates[(nc >> 8) * 1280u + (unsigned)c_grp[j] * 256u + (nc & 255u)];
        r[k] = v * g;
    }
    reinterpret_cast<float4*>(out)[gid] = make_float4(r[0], r[1], r[2], r[3]);
}

extern "C" void kernel_launch(void* const* d_in, const int* in_sizes, int n_in,
                              void* d_out, int out_size) {
    const float* x  = (const float*)d_in[0];
    const float* W1 = (const float*)d_in[1];
    const float* b1 = (const float*)d_in[2];
    const float* W2 = (const float*)d_in[3];
    const float* b2 = (const float*)d_in[4];
    float* out = (float*)d_out;

    reduce_kernel<<<NCV / 8, 256>>>(x);                // 16384 warps
    mlp_kernel<<<NB * 5, 256>>>(W1, b1, W2, b2);       // 320 blocks
    scale_kernel<<<TOTAL / 4 / 256, 256>>>(x, out);    // 25600 blocks
}

// round 2
// speedup vs baseline: 1.0209x; 1.0209x over previous
#include <cuda_runtime.h>
#include <math.h>

#define NB 64
#define CC 256
#define TT 64
#define VV 25
#define HID 16
#define NCV (NB*CC)            // 16384 (n,c) chunks
#define CHUNK (TT*VV)          // 1600 floats per (n,c)
#define TOTAL (NB*CC*TT*VV)    // 26214400

#define CPB 2                  // chunks per block in scale kernel
#define SCALE_THREADS 256

// scratch (allocation-free rule: __device__ globals)
__device__ float g_avg[NCV];
__device__ float g_mx[NCV];
__device__ float g_gates[NB * 5 * CC];

// output joint -> input joint (TORSO, LEFT_HAND, LEFT_LEG, RIGHT_HAND, RIGHT_LEG)
__constant__ int c_perm[VV] = {0,1,2,3,20,  8,9,10,11,23,24,  16,17,18,19,  4,5,6,7,21,22,  12,13,14,15};
__constant__ int c_grp[VV]  = {0,0,0,0,0,   1,1,1,1,1,1,      2,2,2,2,      3,3,3,3,3,3,    4,4,4,4};

// ---------------- K1: torso mean/max over (T, {0,1,2,3,20}) per (n,c) ----------------
// one warp per (n,c); lane handles t=lane and t=lane+32
__global__ void reduce_kernel(const float* __restrict__ x) {
    int gwarp = (blockIdx.x * blockDim.x + threadIdx.x) >> 5;
    int lane  = threadIdx.x & 31;
    if (gwarp >= NCV) return;
    const float* base = x + (size_t)gwarp * CHUNK;
    float s = 0.f, m = -INFINITY;
#pragma unroll
    for (int half = 0; half < 2; half++) {
        const float* row = base + (lane + half * 32) * VV;
        float v0 = row[0], v1 = row[1], v2 = row[2], v3 = row[3], v4 = row[20];
        s += (v0 + v1) + (v2 + v3) + v4;
        m = fmaxf(m, fmaxf(fmaxf(v0, v1), fmaxf(fmaxf(v2, v3), v4)));
    }
#pragma unroll
    for (int o = 16; o; o >>= 1) {
        s += __shfl_xor_sync(0xffffffffu, s, o);
        m = fmaxf(m, __shfl_xor_sync(0xffffffffu, m, o));
    }
    if (lane == 0) {
        g_avg[gwarp] = s * (1.0f / 320.0f);
        g_mx[gwarp]  = m;
    }
}

// ---------------- K2: per-(n,group) MLP -> gates ----------------
// gate[n,f,c] = sigmoid( (relu(W1·avg+b1) + relu(W1·mx+b1)) · W2[c,:] + 2*b2[c] )
__global__ void mlp_kernel(const float* __restrict__ W1, const float* __restrict__ b1,
                           const float* __restrict__ W2, const float* __restrict__ b2) {
    int blk = blockIdx.x;          // n*5 + f
    int n = blk / 5, f = blk % 5;
    __shared__ float pa[CC], pm[CC], hs[HID];
    int tid = threadIdx.x;
    pa[tid] = g_avg[n * CC + tid];
    pm[tid] = g_mx[n * CC + tid];
    __syncthreads();

    int w = tid >> 5, lane = tid & 31;   // 8 warps, 2 hidden units each
#pragma unroll
    for (int hh = 0; hh < 2; hh++) {
        int h = w * 2 + hh;
        const float* w1row = W1 + (f * HID + h) * CC;
        float sa = 0.f, sm = 0.f;
#pragma unroll
        for (int c = lane; c < CC; c += 32) {
            float wv = w1row[c];
            sa = fmaf(wv, pa[c], sa);
            sm = fmaf(wv, pm[c], sm);
        }
#pragma unroll
        for (int o = 16; o; o >>= 1) {
            sa += __shfl_xor_sync(0xffffffffu, sa, o);
            sm += __shfl_xor_sync(0xffffffffu, sm, o);
        }
        if (lane == 0) {
            float b = b1[f * HID + h];
            hs[h] = fmaxf(sa + b, 0.f) + fmaxf(sm + b, 0.f);
        }
    }
    __syncthreads();

    const float* w2row = W2 + ((size_t)f * CC + tid) * HID;
    float o = 2.0f * b2[f * CC + tid];
#pragma unroll
    for (int h = 0; h < HID; h++) o = fmaf(hs[h], w2row[h], o);
    g_gates[n * (5 * CC) + f * CC + tid] = 1.0f / (1.0f + expf(-o));
}

// ---------------- K3: out[n,c,t,j] = x[n,c,t,perm[j]] * gate[n,grp[j],c] ----------------
// SMEM-staged permutation: coalesced float4 in, permute+gate in SMEM, coalesced float4 out.
__global__ __launch_bounds__(SCALE_THREADS) void scale_kernel(const float* __restrict__ x,
                                                              float* __restrict__ out) {
    __shared__ float sx[CPB * CHUNK];   // 2*1600 floats = 12.8 KB
    __shared__ float sg[CPB * 5];
    const int tid = threadIdx.x;
    const int base = blockIdx.x * CPB;                  // first (n,c) chunk of this block
    const float4* __restrict__ src = reinterpret_cast<const float4*>(x + (size_t)base * CHUNK);
    float4* __restrict__ dst = reinterpret_cast<float4*>(out + (size_t)base * CHUNK);

    // coalesced load: CPB*CHUNK/4 = 800 float4s
#pragma unroll
    for (int idx = tid; idx < CPB * CHUNK / 4; idx += SCALE_THREADS) {
        reinterpret_cast<float4*>(sx)[idx] = src[idx];
    }
    // gates for each chunk (CPB*5 = 10 values)
    if (tid < CPB * 5) {
        int cl = tid / 5, f = tid % 5;
        int nc = base + cl;
        sg[tid] = g_gates[(nc >> 8) * (5 * CC) + f * CC + (nc & (CC - 1))];
    }
    __syncthreads();

    // permute + gate + coalesced store
#pragma unroll
    for (int idx = tid; idx < CPB * CHUNK / 4; idx += SCALE_THREADS) {
        int e0 = idx * 4;
        int cl = e0 / CHUNK;                 // chunk-local (0..CPB-1)
        int rem = e0 - cl * CHUNK;
        float r[4];
#pragma unroll
        for (int k = 0; k < 4; k++) {
            int e = rem + k;
            int t = e / VV;
            int j = e - t * VV;
            r[k] = sx[cl * CHUNK + t * VV + c_perm[j]] * sg[cl * 5 + c_grp[j]];
        }
        dst[idx] = make_float4(r[0], r[1], r[2], r[3]);
    }
}

extern "C" void kernel_launch(void* const* d_in, const int* in_sizes, int n_in,
                              void* d_out, int out_size) {
    const float* x  = (const float*)d_in[0];
    const float* W1 = (const float*)d_in[1];
    const float* b1 = (const float*)d_in[2];
    const float* W2 = (const float*)d_in[3];
    const float* b2 = (const float*)d_in[4];
    float* out = (float*)d_out;

    reduce_kernel<<<NCV / 8, 256>>>(x);                 // 16384 warps
    mlp_kernel<<<NB * 5, 256>>>(W1, b1, W2, b2);        // 320 blocks
    scale_kernel<<<NCV / CPB, SCALE_THREADS>>>(x, out); // 8192 blocks
}

// round 3
// speedup vs baseline: 4.9471x; 4.8458x over previous
#include <cuda_runtime.h>
#include <math.h>

#define NB 64
#define CC 256
#define TT 64
#define VV 25
#define HID 16
#define NCV (NB*CC)            // 16384 (n,c) chunks
#define CHUNK (TT*VV)          // 1600 floats per (n,c)
#define TOTAL (NB*CC*TT*VV)    // 26214400

#define CPB 2                  // chunks per block in scale kernel
#define SCALE_THREADS 256

// scratch (allocation-free rule: __device__ globals)
__device__ float g_avg[NCV];
__device__ float g_mx[NCV];
__device__ float g_gates[NB * 5 * CC];

// output joint -> input joint (TORSO, LEFT_HAND, LEFT_LEG, RIGHT_HAND, RIGHT_LEG)
__constant__ int c_perm[VV] = {0,1,2,3,20,  8,9,10,11,23,24,  16,17,18,19,  4,5,6,7,21,22,  12,13,14,15};
__constant__ int c_grp[VV]  = {0,0,0,0,0,   1,1,1,1,1,1,      2,2,2,2,      3,3,3,3,3,3,    4,4,4,4};

// ---------------- K1: torso mean/max over (T, {0,1,2,3,20}) per (n,c) ----------------
__global__ void reduce_kernel(const float* __restrict__ x) {
    int gwarp = (blockIdx.x * blockDim.x + threadIdx.x) >> 5;
    int lane  = threadIdx.x & 31;
    if (gwarp >= NCV) return;
    const float* base = x + (size_t)gwarp * CHUNK;
    float s = 0.f, m = -INFINITY;
#pragma unroll
    for (int half = 0; half < 2; half++) {
        const float* row = base + (lane + half * 32) * VV;
        float v0 = row[0], v1 = row[1], v2 = row[2], v3 = row[3], v4 = row[20];
        s += (v0 + v1) + (v2 + v3) + v4;
        m = fmaxf(m, fmaxf(fmaxf(v0, v1), fmaxf(fmaxf(v2, v3), v4)));
    }
#pragma unroll
    for (int o = 16; o; o >>= 1) {
        s += __shfl_xor_sync(0xffffffffu, s, o);
        m = fmaxf(m, __shfl_xor_sync(0xffffffffu, m, o));
    }
    if (lane == 0) {
        g_avg[gwarp] = s * (1.0f / 320.0f);
        g_mx[gwarp]  = m;
    }
}

// ---------------- K2: per-(n,group) MLP -> gates ----------------
__global__ void mlp_kernel(const float* __restrict__ W1, const float* __restrict__ b1,
                           const float* __restrict__ W2, const float* __restrict__ b2) {
    int blk = blockIdx.x;          // n*5 + f
    int n = blk / 5, f = blk % 5;
    __shared__ float pa[CC], pm[CC], hs[HID];
    int tid = threadIdx.x;
    pa[tid] = g_avg[n * CC + tid];
    pm[tid] = g_mx[n * CC + tid];
    __syncthreads();

    int w = tid >> 5, lane = tid & 31;   // 8 warps, 2 hidden units each
#pragma unroll
    for (int hh = 0; hh < 2; hh++) {
        int h = w * 2 + hh;
        const float* w1row = W1 + (f * HID + h) * CC;
        float sa = 0.f, sm = 0.f;
#pragma unroll
        for (int c = lane; c < CC; c += 32) {
            float wv = w1row[c];
            sa = fmaf(wv, pa[c], sa);
            sm = fmaf(wv, pm[c], sm);
        }
#pragma unroll
        for (int o = 16; o; o >>= 1) {
            sa += __shfl_xor_sync(0xffffffffu, sa, o);
            sm += __shfl_xor_sync(0xffffffffu, sm, o);
        }
        if (lane == 0) {
            float b = b1[f * HID + h];
            hs[h] = fmaxf(sa + b, 0.f) + fmaxf(sm + b, 0.f);
        }
    }
    __syncthreads();

    const float* w2row = W2 + ((size_t)f * CC + tid) * HID;
    float o = 2.0f * b2[f * CC + tid];
#pragma unroll
    for (int h = 0; h < HID; h++) o = fmaf(hs[h], w2row[h], o);
    g_gates[n * (5 * CC) + f * CC + tid] = 1.0f / (1.0f + expf(-o));
}

// ---------------- K3: out[n,c,t,j] = x[n,c,t,perm[j]] * gate[n,grp[j],c] ----------------
// SMEM-staged permutation; perm + per-chunk gate tables in SHARED memory (no divergent LDC
// in the hot loop — dynamic-index __constant__ serializes on the constant port).
__global__ __launch_bounds__(SCALE_THREADS) void scale_kernel(const float* __restrict__ x,
                                                              float* __restrict__ out) {
    __shared__ float sx[CPB * CHUNK];   // 2*1600 floats = 12.8 KB
    __shared__ float sgate[CPB * 32];   // gate value per (chunk, output joint), padded stride
    __shared__ int   sperm[32];
    const int tid = threadIdx.x;
    const int base = blockIdx.x * CPB;                  // first (n,c) chunk of this block
    const float4* __restrict__ src = reinterpret_cast<const float4*>(x + (size_t)base * CHUNK);
    float4* __restrict__ dst = reinterpret_cast<float4*>(out + (size_t)base * CHUNK);

    if (tid < VV) sperm[tid] = c_perm[tid];             // uniform-ish, once per block
    if (tid >= 32 && tid < 32 + CPB * VV) {
        int q = tid - 32, cl = q / VV, j = q - cl * VV;
        int nc = base + cl;
        sgate[cl * 32 + j] = g_gates[(nc >> 8) * (5 * CC) + c_grp[j] * CC + (nc & (CC - 1))];
    }

    // coalesced load: CPB*CHUNK/4 = 800 float4s
#pragma unroll
    for (int idx = tid; idx < CPB * CHUNK / 4; idx += SCALE_THREADS) {
        reinterpret_cast<float4*>(sx)[idx] = src[idx];
    }
    __syncthreads();

    // permute + gate + coalesced store (SMEM-only lookups in the hot loop)
#pragma unroll
    for (int idx = tid; idx < CPB * CHUNK / 4; idx += SCALE_THREADS) {
        int e0 = idx * 4;
        int cl = e0 / CHUNK;                 // chunk-local (0..CPB-1)
        int rem = e0 - cl * CHUNK;
        float r[4];
#pragma unroll
        for (int k = 0; k < 4; k++) {
            int e = rem + k;
            int t = e / VV;
            int j = e - t * VV;
            r[k] = sx[cl * CHUNK + t * VV + sperm[j]] * sgate[cl * 32 + j];
        }
        dst[idx] = make_float4(r[0], r[1], r[2], r[3]);
    }
}

extern "C" void kernel_launch(void* const* d_in, const int* in_sizes, int n_in,
                              void* d_out, int out_size) {
    const float* x  = (const float*)d_in[0];
    const float* W1 = (const float*)d_in[1];
    const float* b1 = (const float*)d_in[2];
    const float* W2 = (const float*)d_in[3];
    const float* b2 = (const float*)d_in[4];
    float* out = (float*)d_out;

    reduce_kernel<<<NCV / 8, 256>>>(x);                 // 16384 warps
    mlp_kernel<<<NB * 5, 256>>>(W1, b1, W2, b2);        // 320 blocks
    scale_kernel<<<NCV / CPB, SCALE_THREADS>>>(x, out); // 8192 blocks
}